// round 7
// baseline (speedup 1.0000x reference)
#include <cuda_runtime.h>
#include <math.h>

#define BB   4
#define TT0  128
#define WD   128
#define EB   16
#define LL   2048
#define ODIM 24
#define TF   122

// ---------------- scratch (no allocations allowed) ----------------
__device__ float g_bufA[BB*WD*TT0*EB];   // 4 MB
__device__ float g_bufB[BB*WD*TT0*EB];   // 4 MB
__device__ float g_Mt[2*WD*WD];          // Mt[m*128+n] = (Wq Wk^T)[n][m]
__device__ float g_uu[2*WD];             // u = Wq bk
__device__ float g_ww[2*WD];             // w = Wk bq
__device__ float g_cc[2];                // c = bq . bk
__device__ float g_yv[BB*126*WD];        // per-(b,t) y vectors

// ---------------- f32x2 packed helpers ----------------
__device__ __forceinline__ unsigned long long fma2(unsigned long long a,
                                                   unsigned long long b,
                                                   unsigned long long c) {
    unsigned long long d;
    asm("fma.rn.f32x2 %0, %1, %2, %3;" : "=l"(d) : "l"(a), "l"(b), "l"(c));
    return d;
}
__device__ __forceinline__ unsigned long long pack2(float v) {
    unsigned long long r;
    asm("mov.b64 %0, {%1, %1};" : "=l"(r) : "f"(v));
    return r;
}
__device__ __forceinline__ void unpack2(unsigned long long v, float& lo, float& hi) {
    asm("mov.b64 {%0, %1}, %2;" : "=f"(lo), "=f"(hi) : "l"(v));
}

// ---------------- embed: x_in -> (B,N,T,E) ----------------
__global__ void k_embed(const float* __restrict__ x_in,
                        const float* __restrict__ emb_w,
                        const float* __restrict__ emb_b,
                        float* __restrict__ out) {
    int idx = blockIdx.x*blockDim.x + threadIdx.x;   // over B*T*N
    if (idx >= BB*TT0*WD) return;
    int n = idx & 127;
    int t = (idx >> 7) & 127;
    int b = idx >> 14;
    const float* xi = x_in + (b*TT0 + t)*131;
    float v  = xi[n];
    float f0 = xi[128], f1 = xi[129], f2 = xi[130];
    float* o = out + ((b*WD + n)*TT0 + t)*EB;
    #pragma unroll
    for (int e = 0; e < EB; e++)
        o[e] = v*emb_w[e] + f0*emb_w[16+e] + f1*emb_w[32+e] + f2*emb_w[48+e] + emb_b[e];
}

// ---------------- precompute Mt[m*128+n] = sum_l Wq[n,l]*Wk[m,l], both layers ----------------
__global__ void k_mt(const float* __restrict__ Wq0, const float* __restrict__ Wk0,
                     const float* __restrict__ Wq1, const float* __restrict__ Wk1,
                     float* __restrict__ Mt) {
    __shared__ float Aq[16][65], Ak[16][65];
    int ly = blockIdx.y;
    const float* Wq = ly ? Wq1 : Wq0;
    const float* Wk = ly ? Wk1 : Wk0;
    float* Mto = Mt + ly*WD*WD;
    int bm = blockIdx.x >> 3, bn = blockIdx.x & 7;
    int m0 = bm*16, n0 = bn*16;
    int ty = threadIdx.x >> 4, tx = threadIdx.x & 15;  // ty -> m, tx -> n
    float acc = 0.f;
    for (int l0 = 0; l0 < LL; l0 += 64) {
        #pragma unroll
        for (int r = 0; r < 4; r++) {
            int idx = threadIdx.x + r*256;
            int row = idx >> 6, col = idx & 63;
            Aq[row][col] = Wq[(n0+row)*LL + l0 + col];
            Ak[row][col] = Wk[(m0+row)*LL + l0 + col];
        }
        __syncthreads();
        #pragma unroll
        for (int lc = 0; lc < 64; lc++)
            acc += Ak[ty][lc]*Aq[tx][lc];
        __syncthreads();
    }
    Mto[(m0+ty)*WD + (n0+tx)] = acc;
}

// ---------------- precompute u, w, c (both layers) ----------------
__global__ void k_uw(const float* __restrict__ Wq0, const float* __restrict__ Wk0,
                     const float* __restrict__ bq0, const float* __restrict__ bk0,
                     const float* __restrict__ Wq1, const float* __restrict__ Wk1,
                     const float* __restrict__ bq1, const float* __restrict__ bk1,
                     float* __restrict__ u, float* __restrict__ w, float* __restrict__ cp) {
    int ly = blockIdx.y;
    const float* Wq = ly ? Wq1 : Wq0;
    const float* Wk = ly ? Wk1 : Wk0;
    const float* bq = ly ? bq1 : bq0;
    const float* bk = ly ? bk1 : bk0;
    int n = blockIdx.x;
    __shared__ float su[256], sw[256], sc[256];
    float pu = 0.f, pw = 0.f, pc = 0.f;
    for (int l = threadIdx.x; l < LL; l += 256) {
        float bkl = bk[l], bql = bq[l];
        pu += Wq[n*LL + l]*bkl;
        pw += Wk[n*LL + l]*bql;
        if (n == 0) pc += bql*bkl;
    }
    su[threadIdx.x] = pu; sw[threadIdx.x] = pw; sc[threadIdx.x] = pc;
    __syncthreads();
    for (int s = 128; s > 0; s >>= 1) {
        if (threadIdx.x < s) {
            su[threadIdx.x] += su[threadIdx.x + s];
            sw[threadIdx.x] += sw[threadIdx.x + s];
            sc[threadIdx.x] += sc[threadIdx.x + s];
        }
        __syncthreads();
    }
    if (threadIdx.x == 0) {
        u[ly*WD + n] = su[0]; w[ly*WD + n] = sw[0];
        if (n == 0) cp[ly] = sc[0];
    }
}

// ---------------- gated conv v5: TT=2 for grid/occupancy ----------------
// Block: 128 thr = 64 ol x 2 eql; handles (o-half, e-half) of one 2-wide time tile.
template<int TIN, int TOUT, int D>
__global__ void k_gated5(const float* __restrict__ X,
                         const float* __restrict__ wf, const float* __restrict__ bf,
                         const float* __restrict__ wg, const float* __restrict__ bg,
                         float* __restrict__ Y) {
    constexpr int TT = 2;
    constexpr int WIDTH = TT + D;
    constexpr int C = 16;          // i-chunk
    constexpr int WROW = 65;       // padded row for [ict][o_local]
    extern __shared__ float sm[];
    float* Xs  = sm;                          // [128][WIDTH][8]
    float* Wfs = sm + WD*WIDTH*8;             // [2*C][WROW]
    float* Wgs = Wfs + 2*C*WROW;              // [2*C][WROW]

    const int ntile = (TOUT + TT - 1)/TT;
    int bid = blockIdx.x;
    int be  = bid & 1;                        // e-half
    int bo  = (bid >> 1) & 1;                 // o-half
    int bt  = bid >> 2;
    int b   = bt / ntile;
    int t0  = (bt % ntile)*TT;
    int tid = threadIdx.x;                    // 128
    int ol  = tid >> 1;                       // 0..63
    int o   = bo*64 + ol;
    int eql = tid & 1;                        // quad within e-half
    int e0  = be*8;

    // cooperative X tile load: [i][w][8e], float4 granularity
    for (int idx = tid; idx < WD*WIDTH*2; idx += 128) {
        int q = idx & 1;
        int w = (idx >> 1) % WIDTH;
        int i = idx / (2*WIDTH);
        int t = t0 + w;
        float4 v = make_float4(0.f, 0.f, 0.f, 0.f);
        if (t < TIN) v = *(const float4*)(X + ((b*WD + i)*TIN + t)*16 + e0 + q*4);
        *(float4*)(Xs + (i*WIDTH + w)*8 + q*4) = v;
    }

    unsigned long long fa[TT][2], ga[TT][2];
    #pragma unroll
    for (int t = 0; t < TT; t++) { fa[t][0]=0ull; fa[t][1]=0ull; ga[t][0]=0ull; ga[t][1]=0ull; }

    for (int i0 = 0; i0 < WD; i0 += C) {
        __syncthreads();   // also covers initial X load; protects Wfs reuse
        for (int idx = tid; idx < 64*2*C; idx += 128) {
            int o2 = idx >> 5, ict = idx & 31;
            Wfs[ict*WROW + o2] = wf[(bo*64 + o2)*(WD*2) + i0*2 + ict];
            Wgs[ict*WROW + o2] = wg[(bo*64 + o2)*(WD*2) + i0*2 + ict];
        }
        __syncthreads();
        #pragma unroll
        for (int ic = 0; ic < C; ic++) {
            int i = i0 + ic;
            unsigned long long pf0 = pack2(Wfs[(ic*2+0)*WROW + ol]);
            unsigned long long pf1 = pack2(Wfs[(ic*2+1)*WROW + ol]);
            unsigned long long pg0 = pack2(Wgs[(ic*2+0)*WROW + ol]);
            unsigned long long pg1 = pack2(Wgs[(ic*2+1)*WROW + ol]);
            unsigned long long x[WIDTH][2];
            #pragma unroll
            for (int w = 0; w < WIDTH; w++) {
                ulonglong2 v = *(const ulonglong2*)(Xs + (i*WIDTH + w)*8 + eql*4);
                x[w][0] = v.x; x[w][1] = v.y;
            }
            #pragma unroll
            for (int t = 0; t < TT; t++) {
                fa[t][0] = fma2(pf0, x[t][0],   fa[t][0]);
                fa[t][1] = fma2(pf0, x[t][1],   fa[t][1]);
                fa[t][0] = fma2(pf1, x[t+D][0], fa[t][0]);
                fa[t][1] = fma2(pf1, x[t+D][1], fa[t][1]);
                ga[t][0] = fma2(pg0, x[t][0],   ga[t][0]);
                ga[t][1] = fma2(pg0, x[t][1],   ga[t][1]);
                ga[t][0] = fma2(pg1, x[t+D][0], ga[t][0]);
                ga[t][1] = fma2(pg1, x[t+D][1], ga[t][1]);
            }
        }
    }

    float bfo = bf[o], bgo = bg[o];
    #pragma unroll
    for (int t = 0; t < TT; t++) {
        int tt = t0 + t;
        if (tt < TOUT) {
            float f0,f1,f2,f3, g0,g1,g2,g3;
            unpack2(fa[t][0], f0, f1); unpack2(fa[t][1], f2, f3);
            unpack2(ga[t][0], g0, g1); unpack2(ga[t][1], g2, g3);
            float4 r;
            r.x = tanhf(f0 + bfo)*(1.f/(1.f + expf(-(g0 + bgo))));
            r.y = tanhf(f1 + bfo)*(1.f/(1.f + expf(-(g1 + bgo))));
            r.z = tanhf(f2 + bfo)*(1.f/(1.f + expf(-(g2 + bgo))));
            r.w = tanhf(f3 + bfo)*(1.f/(1.f + expf(-(g3 + bgo))));
            *(float4*)(Y + ((b*WD + o)*TOUT + tt)*16 + e0 + eql*4) = r;
        }
    }
}

// ---------------- gated residual v2: tiled smem GEMM ----------------
template<int TIN, int TOUT>
__global__ void k_res2(const float* __restrict__ X, const float* __restrict__ ws,
                       const float* __restrict__ bs, float* __restrict__ Y) {
    constexpr int RPB = 64;
    constexpr int KC  = 32;
    __shared__ float As[KC][RPB];       // [t][row]
    __shared__ float Ws[KC][132];       // [t][s], 16B-aligned rows
    int b  = blockIdx.x >> 5;
    int r0 = (blockIdx.x & 31)*RPB;
    int tid = threadIdx.x;              // 256
    int rq = tid >> 4;                  // 0..15 -> rows rq*4..+3
    int sg = tid & 15;                  // s = sg*8 .. +7

    unsigned long long acc[4][4];
    #pragma unroll
    for (int r = 0; r < 4; r++)
        #pragma unroll
        for (int j = 0; j < 4; j++) acc[r][j] = 0ull;

    for (int t0 = 0; t0 < TIN; t0 += KC) {
        __syncthreads();
        #pragma unroll
        for (int j = 0; j < (RPB*KC)/256; j++) {
            int idx = tid + j*256;
            int row = idx & (RPB-1);
            int t = idx >> 6;
            int rr = r0 + row;
            int n = rr >> 4, e = rr & 15;
            int tg = t0 + t;
            As[t][row] = (tg < TIN) ? X[((b*WD + n)*TIN + tg)*EB + e] : 0.f;
        }
        #pragma unroll
        for (int j = 0; j < (KC*128)/256; j++) {
            int idx = tid + j*256;
            int s = idx & 127;
            int t = idx >> 7;
            int tg = t0 + t;
            Ws[t][s] = (tg < TIN && s < TOUT) ? ws[tg*TOUT + s] : 0.f;
        }
        __syncthreads();
        #pragma unroll
        for (int t = 0; t < KC; t++) {
            float4 w0 = *(const float4*)(&Ws[t][sg*8]);
            float4 w1 = *(const float4*)(&Ws[t][sg*8 + 4]);
            unsigned long long wv[4];
            wv[0] = ((unsigned long long)__float_as_uint(w0.y) << 32) | __float_as_uint(w0.x);
            wv[1] = ((unsigned long long)__float_as_uint(w0.w) << 32) | __float_as_uint(w0.z);
            wv[2] = ((unsigned long long)__float_as_uint(w1.y) << 32) | __float_as_uint(w1.x);
            wv[3] = ((unsigned long long)__float_as_uint(w1.w) << 32) | __float_as_uint(w1.z);
            #pragma unroll
            for (int r = 0; r < 4; r++) {
                unsigned long long av = pack2(As[t][rq*4 + r]);
                #pragma unroll
                for (int j = 0; j < 4; j++)
                    acc[r][j] = fma2(av, wv[j], acc[r][j]);
            }
        }
    }
    #pragma unroll
    for (int r = 0; r < 4; r++) {
        int rr = r0 + rq*4 + r;
        int n = rr >> 4, e = rr & 15;
        float* yp = Y + ((size_t)(b*WD + n)*TOUT)*EB + e;
        #pragma unroll
        for (int j = 0; j < 4; j++) {
            float lo, hi; unpack2(acc[r][j], lo, hi);
            int s0 = sg*8 + j*2;
            if (s0 < TOUT)   yp[s0*EB]       += lo + bs[s0];
            if (s0+1 < TOUT) yp[(s0+1)*EB]   += hi + bs[s0+1];
        }
    }
}

// ---------------- fused attention: Z (in-block GEMM) + softmax + ybar ----------------
template<int T>
__global__ void k_attn2(const float* __restrict__ X, const float* __restrict__ Mt,
                        const float* __restrict__ u, const float* __restrict__ w,
                        const float* __restrict__ cptr, float* __restrict__ yout) {
    __shared__ __align__(16) float Xs[WD*EB];   // [n][e] 8KB
    __shared__ __align__(16) float Ms[32*WD];   // Mt chunk [k][n] 16KB
    __shared__ float Zs[EB][WD+5];              // [f][n]
    __shared__ float Ss[EB][EB+1];
    __shared__ float uev[EB], wfv[EB], abar[EB];
    int bt = blockIdx.x;
    int b = bt / T, t = bt % T;
    int tid = threadIdx.x;                      // 256
    // load Xs (vectorized)
    for (int idx = tid; idx < WD*4; idx += 256) {
        int n = idx >> 2, q = idx & 3;
        ((float4*)Xs)[idx] = *(const float4*)(X + ((b*WD + n)*T + t)*EB + q*4);
    }
    // Z[fh*8..+7][n] per thread (n = tid&127, fh = tid>>7)
    int n_ = tid & 127, fh = tid >> 7;
    unsigned long long zacc[4] = {0ull, 0ull, 0ull, 0ull};
    for (int m0 = 0; m0 < WD; m0 += 32) {
        __syncthreads();
        #pragma unroll
        for (int rep = 0; rep < (32*WD/4)/256; rep++)
            ((float4*)Ms)[tid + rep*256] = ((const float4*)(Mt + m0*WD))[tid + rep*256];
        __syncthreads();
        #pragma unroll
        for (int k = 0; k < 32; k++) {
            unsigned long long pm = pack2(Ms[k*WD + n_]);
            const ulonglong2* xp = (const ulonglong2*)(Xs + (m0 + k)*16 + fh*8);
            ulonglong2 xa = xp[0];
            zacc[0] = fma2(pm, xa.x, zacc[0]);
            zacc[1] = fma2(pm, xa.y, zacc[1]);
            ulonglong2 xb = xp[1];
            zacc[2] = fma2(pm, xb.x, zacc[2]);
            zacc[3] = fma2(pm, xb.y, zacc[3]);
        }
    }
    #pragma unroll
    for (int j = 0; j < 4; j++) {
        float lo, hi; unpack2(zacc[j], lo, hi);
        Zs[fh*8 + 2*j][n_]     = lo;
        Zs[fh*8 + 2*j + 1][n_] = hi;
    }
    if (tid < 16) {
        float a = 0.f;
        for (int n = 0; n < WD; n++) a += Xs[n*16 + tid]*u[n];
        uev[tid] = a;
    } else if (tid < 32) {
        int f = tid - 16;
        float a = 0.f;
        for (int n = 0; n < WD; n++) a += Xs[n*16 + f]*w[n];
        wfv[f] = a;
    }
    __syncthreads();
    {
        int e = tid >> 4, f = tid & 15;
        float acc = 0.f;
        #pragma unroll 4
        for (int n = 0; n < WD; n++)
            acc += Xs[n*16 + e]*Zs[f][n];
        const float scale = 0.022097086912079608f; // 1/sqrt(2048)
        Ss[e][f] = (acc + uev[e] + wfv[f] + cptr[0])*scale;
    }
    __syncthreads();
    if (tid < 16) {
        int e = tid;
        float mx = -1e30f;
        #pragma unroll
        for (int f = 0; f < 16; f++) mx = fmaxf(mx, Ss[e][f]);
        float ex[16]; float sum = 0.f;
        #pragma unroll
        for (int f = 0; f < 16; f++) { ex[f] = expf(Ss[e][f] - mx); sum += ex[f]; }
        float inv = 1.f/sum;
        #pragma unroll
        for (int f = 0; f < 16; f++) Ss[e][f] = ex[f]*inv;
    }
    __syncthreads();
    if (tid < 16) {
        int f = tid;
        float a = 0.f;
        #pragma unroll
        for (int e = 0; e < 16; e++) a += Ss[e][f];
        abar[f] = a*(1.f/16.f);
    }
    __syncthreads();
    if (tid < 128) {
        int n = tid;
        float a = 0.f;
        #pragma unroll
        for (int f = 0; f < 16; f++) a += Xs[n*16 + f]*abar[f];
        yout[bt*WD + n] = a;
    }
}

// ---------------- attention out: Y = X + y @ Wv + bv ----------------
template<int T>
__global__ void k_attn_out(const float* __restrict__ Xin, const float* __restrict__ yv,
                           const float* __restrict__ Wv, const float* __restrict__ bv,
                           float* __restrict__ Yout) {
    __shared__ float ys[64][WD];
    const int BT = BB*T;
    int bt0 = blockIdx.y*64;
    int l = blockIdx.x*128 + (threadIdx.x & 127);
    int half = threadIdx.x >> 7;
    for (int idx = threadIdx.x; idx < 64*WD; idx += 256) {
        int r = idx >> 7, m = idx & 127;
        int bt = bt0 + r;
        ys[r][m] = (bt < BT) ? yv[bt*WD + m] : 0.f;
    }
    __syncthreads();
    float acc[32];
    #pragma unroll
    for (int j = 0; j < 32; j++) acc[j] = 0.f;
    for (int m = 0; m < WD; m++) {
        float wvv = Wv[m*LL + l];
        #pragma unroll
        for (int j = 0; j < 32; j++) acc[j] += ys[half*32 + j][m]*wvv;
    }
    float bvl = bv[l];
    int n = l >> 4, e = l & 15;
    #pragma unroll
    for (int j = 0; j < 32; j++) {
        int bt = bt0 + half*32 + j;
        if (bt < BT) {
            int b = bt / T, t = bt % T;
            int idx = ((b*WD + n)*T + t)*EB + e;
            Yout[idx] = Xin[idx] + acc[j] + bvl;
        }
    }
}

// ---------------- decode + time-mix output ----------------
__global__ void k_decode(const float* __restrict__ X, const float* __restrict__ dec_w,
                         const float* __restrict__ dec_b, const float* __restrict__ out_w,
                         const float* __restrict__ out_b, float* __restrict__ out) {
    __shared__ float sy[TF];
    int b = blockIdx.x >> 7, n = blockIdx.x & 127;
    int t = threadIdx.x;
    if (t < TF) {
        const float* xp = X + ((size_t)(b*WD + n)*TF + t)*EB;
        float a = dec_b[n];
        #pragma unroll
        for (int e = 0; e < EB; e++) a += xp[e]*dec_w[n*EB + e];
        sy[t] = a;
    }
    __syncthreads();
    if (t < ODIM) {
        float a = out_b[t];
        for (int tt = 0; tt < TF; tt++) a += sy[tt]*out_w[tt*ODIM + t];
        out[(b*ODIM + t)*WD + n] = a;
    }
}

// ---------------- launcher ----------------
extern "C" void kernel_launch(void* const* d_in, const int* in_sizes, int n_in,
                              void* d_out, int out_size) {
    const float* x_in  = (const float*)d_in[0];
    const float* emb_w = (const float*)d_in[1];
    const float* emb_b = (const float*)d_in[2];
    const float* g0_wf = (const float*)d_in[3];
    const float* g0_bf = (const float*)d_in[4];
    const float* g0_wg = (const float*)d_in[5];
    const float* g0_bg = (const float*)d_in[6];
    const float* g0_ws = (const float*)d_in[7];
    const float* g0_bs = (const float*)d_in[8];
    const float* a0_wq = (const float*)d_in[9];
    const float* a0_bq = (const float*)d_in[10];
    const float* a0_wk = (const float*)d_in[11];
    const float* a0_bk = (const float*)d_in[12];
    const float* a0_wv = (const float*)d_in[13];
    const float* a0_bv = (const float*)d_in[14];
    const float* g1_wf = (const float*)d_in[15];
    const float* g1_bf = (const float*)d_in[16];
    const float* g1_wg = (const float*)d_in[17];
    const float* g1_bg = (const float*)d_in[18];
    const float* g1_ws = (const float*)d_in[19];
    const float* g1_bs = (const float*)d_in[20];
    const float* a1_wq = (const float*)d_in[21];
    const float* a1_bq = (const float*)d_in[22];
    const float* a1_wk = (const float*)d_in[23];
    const float* a1_bk = (const float*)d_in[24];
    const float* a1_wv = (const float*)d_in[25];
    const float* a1_bv = (const float*)d_in[26];
    const float* dec_w = (const float*)d_in[27];
    const float* dec_b = (const float*)d_in[28];
    const float* out_w = (const float*)d_in[29];
    const float* out_b = (const float*)d_in[30];

    float *dA, *dB, *dMt, *dU, *dW, *dC, *dY;
    cudaGetSymbolAddress((void**)&dA,  g_bufA);
    cudaGetSymbolAddress((void**)&dB,  g_bufB);
    cudaGetSymbolAddress((void**)&dMt, g_Mt);
    cudaGetSymbolAddress((void**)&dU,  g_uu);
    cudaGetSymbolAddress((void**)&dW,  g_ww);
    cudaGetSymbolAddress((void**)&dC,  g_cc);
    cudaGetSymbolAddress((void**)&dY,  g_yv);

    // smem sizes for gated5 (TT=2): X [128][W][8] + weights 2*[32][65] (<48KB, no attr)
    const int SMEM_G0 = (WD*4*8 + 2*2*16*65)*4;    // 16384 + 16640 = 33024
    const int SMEM_G1 = (WD*6*8 + 2*2*16*65)*4;    // 24576 + 16640 = 41216

    // embed + attention precompute (merged launches)
    k_embed<<<(BB*TT0*WD + 255)/256, 256>>>(x_in, emb_w, emb_b, dA);
    k_mt<<<dim3(64,2), 256>>>(a0_wq, a0_wk, a1_wq, a1_wk, dMt);
    k_uw<<<dim3(128,2), 256>>>(a0_wq, a0_wk, a0_bq, a0_bk,
                               a1_wq, a1_wk, a1_bq, a1_bk, dU, dW, dC);

    // layer 0: gated (TIN=128 -> 126, d=2), attention T=126
    {
        const int ntile = (126 + 1)/2;  // 63
        k_gated5<128,126,2><<<BB*ntile*4, 128, SMEM_G0>>>(dA, g0_wf, g0_bf, g0_wg, g0_bg, dB);
        k_res2<128,126><<<BB*32, 256>>>(dA, g0_ws, g0_bs, dB);
        k_attn2<126><<<BB*126, 256>>>(dB, dMt, dU, dW, dC, dY);
        k_attn_out<126><<<dim3(16, (BB*126 + 63)/64), 256>>>(dB, dY, a0_wv, a0_bv, dA);
    }

    // layer 1: gated (TIN=126 -> 122, d=4), attention T=122
    {
        const int ntile = (122 + 1)/2;  // 61
        k_gated5<126,122,4><<<BB*ntile*4, 128, SMEM_G1>>>(dA, g1_wf, g1_bf, g1_wg, g1_bg, dB);
        k_res2<126,122><<<BB*32, 256>>>(dA, g1_ws, g1_bs, dB);
        k_attn2<122><<<BB*122, 256>>>(dB, dMt + WD*WD, dU + WD, dW + WD, dC + 1, dY);
        k_attn_out<122><<<dim3(16, (BB*122 + 63)/64), 256>>>(dB, dY, a1_wv, a1_bv, dA);
    }

    // decode
    k_decode<<<BB*WD, 128>>>(dA, dec_w, dec_b, out_w, out_b, (float*)d_out);
}

// round 8
// speedup vs baseline: 1.0538x; 1.0538x over previous
#include <cuda_runtime.h>
#include <math.h>

#define BB   4
#define TT0  128
#define WD   128
#define EB   16
#define LL   2048
#define ODIM 24
#define TF   122

// ---------------- scratch (no allocations allowed) ----------------
__device__ float g_bufA[BB*WD*TT0*EB];   // 4 MB
__device__ float g_bufB[BB*WD*TT0*EB];   // 4 MB
__device__ float g_Mt[2*WD*WD];          // Mt[m*128+n] = (Wq Wk^T)[n][m]
__device__ float g_uu[2*WD];             // u = Wq bk
__device__ float g_ww[2*WD];             // w = Wk bq
__device__ float g_cc[2];                // c = bq . bk
__device__ float g_yv[BB*126*WD];        // per-(b,t) y vectors

// ---------------- f32x2 packed helpers ----------------
__device__ __forceinline__ unsigned long long fma2(unsigned long long a,
                                                   unsigned long long b,
                                                   unsigned long long c) {
    unsigned long long d;
    asm("fma.rn.f32x2 %0, %1, %2, %3;" : "=l"(d) : "l"(a), "l"(b), "l"(c));
    return d;
}
__device__ __forceinline__ unsigned long long pack2(float v) {
    unsigned long long r;
    asm("mov.b64 %0, {%1, %1};" : "=l"(r) : "f"(v));
    return r;
}
__device__ __forceinline__ void unpack2(unsigned long long v, float& lo, float& hi) {
    asm("mov.b64 {%0, %1}, %2;" : "=f"(lo), "=f"(hi) : "l"(v));
}

// ---------------- embed: x_in -> (B,N,T,E) ----------------
__global__ void k_embed(const float* __restrict__ x_in,
                        const float* __restrict__ emb_w,
                        const float* __restrict__ emb_b,
                        float* __restrict__ out) {
    int idx = blockIdx.x*blockDim.x + threadIdx.x;   // over B*T*N
    if (idx >= BB*TT0*WD) return;
    int n = idx & 127;
    int t = (idx >> 7) & 127;
    int b = idx >> 14;
    const float* xi = x_in + (b*TT0 + t)*131;
    float v  = xi[n];
    float f0 = xi[128], f1 = xi[129], f2 = xi[130];
    float* o = out + ((b*WD + n)*TT0 + t)*EB;
    #pragma unroll
    for (int e = 0; e < EB; e++)
        o[e] = v*emb_w[e] + f0*emb_w[16+e] + f1*emb_w[32+e] + f2*emb_w[48+e] + emb_b[e];
}

// ---------------- precompute Mt[m*128+n] = sum_l Wq[n,l]*Wk[m,l], both layers ----------------
__global__ void k_mt(const float* __restrict__ Wq0, const float* __restrict__ Wk0,
                     const float* __restrict__ Wq1, const float* __restrict__ Wk1,
                     float* __restrict__ Mt) {
    __shared__ float Aq[16][65], Ak[16][65];
    int ly = blockIdx.y;
    const float* Wq = ly ? Wq1 : Wq0;
    const float* Wk = ly ? Wk1 : Wk0;
    float* Mto = Mt + ly*WD*WD;
    int bm = blockIdx.x >> 3, bn = blockIdx.x & 7;
    int m0 = bm*16, n0 = bn*16;
    int ty = threadIdx.x >> 4, tx = threadIdx.x & 15;  // ty -> m, tx -> n
    float acc = 0.f;
    for (int l0 = 0; l0 < LL; l0 += 64) {
        #pragma unroll
        for (int r = 0; r < 4; r++) {
            int idx = threadIdx.x + r*256;
            int row = idx >> 6, col = idx & 63;
            Aq[row][col] = Wq[(n0+row)*LL + l0 + col];
            Ak[row][col] = Wk[(m0+row)*LL + l0 + col];
        }
        __syncthreads();
        #pragma unroll
        for (int lc = 0; lc < 64; lc++)
            acc += Ak[ty][lc]*Aq[tx][lc];
        __syncthreads();
    }
    Mto[(m0+ty)*WD + (n0+tx)] = acc;
}

// ---------------- precompute u, w, c (both layers) ----------------
__global__ void k_uw(const float* __restrict__ Wq0, const float* __restrict__ Wk0,
                     const float* __restrict__ bq0, const float* __restrict__ bk0,
                     const float* __restrict__ Wq1, const float* __restrict__ Wk1,
                     const float* __restrict__ bq1, const float* __restrict__ bk1,
                     float* __restrict__ u, float* __restrict__ w, float* __restrict__ cp) {
    int ly = blockIdx.y;
    const float* Wq = ly ? Wq1 : Wq0;
    const float* Wk = ly ? Wk1 : Wk0;
    const float* bq = ly ? bq1 : bq0;
    const float* bk = ly ? bk1 : bk0;
    int n = blockIdx.x;
    __shared__ float su[256], sw[256], sc[256];
    float pu = 0.f, pw = 0.f, pc = 0.f;
    for (int l = threadIdx.x; l < LL; l += 256) {
        float bkl = bk[l], bql = bq[l];
        pu += Wq[n*LL + l]*bkl;
        pw += Wk[n*LL + l]*bql;
        if (n == 0) pc += bql*bkl;
    }
    su[threadIdx.x] = pu; sw[threadIdx.x] = pw; sc[threadIdx.x] = pc;
    __syncthreads();
    for (int s = 128; s > 0; s >>= 1) {
        if (threadIdx.x < s) {
            su[threadIdx.x] += su[threadIdx.x + s];
            sw[threadIdx.x] += sw[threadIdx.x + s];
            sc[threadIdx.x] += sc[threadIdx.x + s];
        }
        __syncthreads();
    }
    if (threadIdx.x == 0) {
        u[ly*WD + n] = su[0]; w[ly*WD + n] = sw[0];
        if (n == 0) cp[ly] = sc[0];
    }
}

// ---------------- gated conv GEMM: F[o,j] = sum_{i,tap} W[o,i,tap] X[i, j+tap*16D] ----
// j = t*16+e flattened per batch. Block tile 64o x 64j, thread 4o x 8j, 128 thr.
// Y[o,j] = tanh(F+bf)*sigmoid(G+bg)
template<int TIN, int TOUT, int D>
__global__ void k_gatedg(const float* __restrict__ X,
                         const float* __restrict__ wf, const float* __restrict__ bf,
                         const float* __restrict__ wg, const float* __restrict__ bg,
                         float* __restrict__ Y) {
    constexpr int TIN16  = TIN*16;
    constexpr int TOUT16 = TOUT*16;
    constexpr int OFF    = 16*D;          // tap-1 column offset (32 or 64)
    __shared__ float Af[64][33];          // [o_local][kk]  kk = il*2+tap
    __shared__ float Ag[64][33];
    __shared__ float Bs[16][136];         // [il][c], c = 0..127

    int bx = blockIdx.x;
    int oB = bx & 1;                      // o-half
    int jT = bx >> 1;                     // j tile
    int b  = blockIdx.y;
    int j0b = jT*64;
    int tid = threadIdx.x;                // 128
    int jt = tid & 7;                     // j-group: j = j0b + jt*8 .. +7
    int ot = tid >> 3;                    // o-group: o_local = ot*4 .. +3

    unsigned long long fa[4][4], ga[4][4];
    #pragma unroll
    for (int oo = 0; oo < 4; oo++)
        #pragma unroll
        for (int p = 0; p < 4; p++) { fa[oo][p] = 0ull; ga[oo][p] = 0ull; }

    for (int i0 = 0; i0 < WD; i0 += 16) {
        __syncthreads();
        // stage weights: Af[ol][kk] = wf[(oB*64+ol)*256 + i0*2 + kk]  (coalesced)
        #pragma unroll
        for (int r = 0; r < 16; r++) {
            int idx = tid + r*128;
            int kk = idx & 31, ol = idx >> 5;
            Af[ol][kk] = wf[(oB*64 + ol)*(WD*2) + i0*2 + kk];
            Ag[ol][kk] = wg[(oB*64 + ol)*(WD*2) + i0*2 + kk];
        }
        // stage X: Bs[il][c] = X[b, i0+il, j0b + c]  (guard input length)
        #pragma unroll
        for (int r = 0; r < 16; r++) {
            int idx = tid + r*128;
            int c = idx & 127, il = idx >> 7;
            int jg = j0b + c;
            Bs[il][c] = (jg < TIN16) ? X[((size_t)(b*WD + i0 + il))*TIN16 + jg] : 0.f;
        }
        __syncthreads();
        #pragma unroll 4
        for (int il = 0; il < 16; il++) {
            #pragma unroll
            for (int tap = 0; tap < 2; tap++) {
                int k = il*2 + tap;
                const float* bp = &Bs[il][jt*8 + tap*OFF];
                ulonglong2 q0 = *(const ulonglong2*)bp;
                ulonglong2 q1 = *(const ulonglong2*)(bp + 4);
                unsigned long long bq[4] = {q0.x, q0.y, q1.x, q1.y};
                #pragma unroll
                for (int oo = 0; oo < 4; oo++) {
                    unsigned long long paf = pack2(Af[ot*4 + oo][k]);
                    unsigned long long pag = pack2(Ag[ot*4 + oo][k]);
                    #pragma unroll
                    for (int p = 0; p < 4; p++) {
                        fa[oo][p] = fma2(paf, bq[p], fa[oo][p]);
                        ga[oo][p] = fma2(pag, bq[p], ga[oo][p]);
                    }
                }
            }
        }
    }

    int jbase = j0b + jt*8;
    if (jbase < TOUT16) {   // TOUT16 % 8 == 0 -> whole 8-j group valid
        #pragma unroll
        for (int oo = 0; oo < 4; oo++) {
            int o = oB*64 + ot*4 + oo;
            float bfo = bf[o], bgo = bg[o];
            float fv[8], gv[8];
            #pragma unroll
            for (int p = 0; p < 4; p++) {
                unpack2(fa[oo][p], fv[2*p], fv[2*p+1]);
                unpack2(ga[oo][p], gv[2*p], gv[2*p+1]);
            }
            float yv[8];
            #pragma unroll
            for (int q = 0; q < 8; q++)
                yv[q] = tanhf(fv[q] + bfo)*(1.f/(1.f + expf(-(gv[q] + bgo))));
            float* yp = Y + ((size_t)(b*WD + o))*TOUT16 + jbase;
            *(float4*)(yp)     = make_float4(yv[0], yv[1], yv[2], yv[3]);
            *(float4*)(yp + 4) = make_float4(yv[4], yv[5], yv[6], yv[7]);
        }
    }
}

// ---------------- gated residual v2: tiled smem GEMM ----------------
template<int TIN, int TOUT>
__global__ void k_res2(const float* __restrict__ X, const float* __restrict__ ws,
                       const float* __restrict__ bs, float* __restrict__ Y) {
    constexpr int RPB = 64;
    constexpr int KC  = 32;
    __shared__ float As[KC][RPB];       // [t][row]
    __shared__ float Ws[KC][132];       // [t][s], 16B-aligned rows
    int b  = blockIdx.x >> 5;
    int r0 = (blockIdx.x & 31)*RPB;
    int tid = threadIdx.x;              // 256
    int rq = tid >> 4;                  // 0..15 -> rows rq*4..+3
    int sg = tid & 15;                  // s = sg*8 .. +7

    unsigned long long acc[4][4];
    #pragma unroll
    for (int r = 0; r < 4; r++)
        #pragma unroll
        for (int j = 0; j < 4; j++) acc[r][j] = 0ull;

    for (int t0 = 0; t0 < TIN; t0 += KC) {
        __syncthreads();
        #pragma unroll
        for (int j = 0; j < (RPB*KC)/256; j++) {
            int idx = tid + j*256;
            int row = idx & (RPB-1);
            int t = idx >> 6;
            int rr = r0 + row;
            int n = rr >> 4, e = rr & 15;
            int tg = t0 + t;
            As[t][row] = (tg < TIN) ? X[((b*WD + n)*TIN + tg)*EB + e] : 0.f;
        }
        #pragma unroll
        for (int j = 0; j < (KC*128)/256; j++) {
            int idx = tid + j*256;
            int s = idx & 127;
            int t = idx >> 7;
            int tg = t0 + t;
            Ws[t][s] = (tg < TIN && s < TOUT) ? ws[tg*TOUT + s] : 0.f;
        }
        __syncthreads();
        #pragma unroll
        for (int t = 0; t < KC; t++) {
            float4 w0 = *(const float4*)(&Ws[t][sg*8]);
            float4 w1 = *(const float4*)(&Ws[t][sg*8 + 4]);
            unsigned long long wv[4];
            wv[0] = ((unsigned long long)__float_as_uint(w0.y) << 32) | __float_as_uint(w0.x);
            wv[1] = ((unsigned long long)__float_as_uint(w0.w) << 32) | __float_as_uint(w0.z);
            wv[2] = ((unsigned long long)__float_as_uint(w1.y) << 32) | __float_as_uint(w1.x);
            wv[3] = ((unsigned long long)__float_as_uint(w1.w) << 32) | __float_as_uint(w1.z);
            #pragma unroll
            for (int r = 0; r < 4; r++) {
                unsigned long long av = pack2(As[t][rq*4 + r]);
                #pragma unroll
                for (int j = 0; j < 4; j++)
                    acc[r][j] = fma2(av, wv[j], acc[r][j]);
            }
        }
    }
    #pragma unroll
    for (int r = 0; r < 4; r++) {
        int rr = r0 + rq*4 + r;
        int n = rr >> 4, e = rr & 15;
        float* yp = Y + ((size_t)(b*WD + n)*TOUT)*EB + e;
        #pragma unroll
        for (int j = 0; j < 4; j++) {
            float lo, hi; unpack2(acc[r][j], lo, hi);
            int s0 = sg*8 + j*2;
            if (s0 < TOUT)   yp[s0*EB]       += lo + bs[s0];
            if (s0+1 < TOUT) yp[(s0+1)*EB]   += hi + bs[s0+1];
        }
    }
}

// ---------------- fused attention: Z (in-block GEMM) + softmax + ybar ----------------
template<int T>
__global__ void k_attn2(const float* __restrict__ X, const float* __restrict__ Mt,
                        const float* __restrict__ u, const float* __restrict__ w,
                        const float* __restrict__ cptr, float* __restrict__ yout) {
    __shared__ __align__(16) float Xs[WD*EB];   // [n][e] 8KB
    __shared__ __align__(16) float Ms[32*WD];   // Mt chunk [k][n] 16KB
    __shared__ float Zs[EB][WD+5];              // [f][n]
    __shared__ float Ss[EB][EB+1];
    __shared__ float uev[EB], wfv[EB], abar[EB];
    int bt = blockIdx.x;
    int b = bt / T, t = bt % T;
    int tid = threadIdx.x;                      // 256
    // load Xs (vectorized)
    for (int idx = tid; idx < WD*4; idx += 256) {
        int n = idx >> 2, q = idx & 3;
        ((float4*)Xs)[idx] = *(const float4*)(X + ((b*WD + n)*T + t)*EB + q*4);
    }
    // Z[fh*8..+7][n] per thread (n = tid&127, fh = tid>>7)
    int n_ = tid & 127, fh = tid >> 7;
    unsigned long long zacc[4] = {0ull, 0ull, 0ull, 0ull};
    for (int m0 = 0; m0 < WD; m0 += 32) {
        __syncthreads();
        #pragma unroll
        for (int rep = 0; rep < (32*WD/4)/256; rep++)
            ((float4*)Ms)[tid + rep*256] = ((const float4*)(Mt + m0*WD))[tid + rep*256];
        __syncthreads();
        #pragma unroll
        for (int k = 0; k < 32; k++) {
            unsigned long long pm = pack2(Ms[k*WD + n_]);
            const ulonglong2* xp = (const ulonglong2*)(Xs + (m0 + k)*16 + fh*8);
            ulonglong2 xa = xp[0];
            zacc[0] = fma2(pm, xa.x, zacc[0]);
            zacc[1] = fma2(pm, xa.y, zacc[1]);
            ulonglong2 xb = xp[1];
            zacc[2] = fma2(pm, xb.x, zacc[2]);
            zacc[3] = fma2(pm, xb.y, zacc[3]);
        }
    }
    #pragma unroll
    for (int j = 0; j < 4; j++) {
        float lo, hi; unpack2(zacc[j], lo, hi);
        Zs[fh*8 + 2*j][n_]     = lo;
        Zs[fh*8 + 2*j + 1][n_] = hi;
    }
    if (tid < 16) {
        float a = 0.f;
        for (int n = 0; n < WD; n++) a += Xs[n*16 + tid]*u[n];
        uev[tid] = a;
    } else if (tid < 32) {
        int f = tid - 16;
        float a = 0.f;
        for (int n = 0; n < WD; n++) a += Xs[n*16 + f]*w[n];
        wfv[f] = a;
    }
    __syncthreads();
    {
        int e = tid >> 4, f = tid & 15;
        float acc = 0.f;
        #pragma unroll 4
        for (int n = 0; n < WD; n++)
            acc += Xs[n*16 + e]*Zs[f][n];
        const float scale = 0.022097086912079608f; // 1/sqrt(2048)
        Ss[e][f] = (acc + uev[e] + wfv[f] + cptr[0])*scale;
    }
    __syncthreads();
    if (tid < 16) {
        int e = tid;
        float mx = -1e30f;
        #pragma unroll
        for (int f = 0; f < 16; f++) mx = fmaxf(mx, Ss[e][f]);
        float ex[16]; float sum = 0.f;
        #pragma unroll
        for (int f = 0; f < 16; f++) { ex[f] = expf(Ss[e][f] - mx); sum += ex[f]; }
        float inv = 1.f/sum;
        #pragma unroll
        for (int f = 0; f < 16; f++) Ss[e][f] = ex[f]*inv;
    }
    __syncthreads();
    if (tid < 16) {
        int f = tid;
        float a = 0.f;
        #pragma unroll
        for (int e = 0; e < 16; e++) a += Ss[e][f];
        abar[f] = a*(1.f/16.f);
    }
    __syncthreads();
    if (tid < 128) {
        int n = tid;
        float a = 0.f;
        #pragma unroll
        for (int f = 0; f < 16; f++) a += Xs[n*16 + f]*abar[f];
        yout[bt*WD + n] = a;
    }
}

// ---------------- attention out: Y = X + y @ Wv + bv ----------------
template<int T>
__global__ void k_attn_out(const float* __restrict__ Xin, const float* __restrict__ yv,
                           const float* __restrict__ Wv, const float* __restrict__ bv,
                           float* __restrict__ Yout) {
    __shared__ float ys[64][WD];
    const int BT = BB*T;
    int bt0 = blockIdx.y*64;
    int l = blockIdx.x*128 + (threadIdx.x & 127);
    int half = threadIdx.x >> 7;
    for (int idx = threadIdx.x; idx < 64*WD; idx += 256) {
        int r = idx >> 7, m = idx & 127;
        int bt = bt0 + r;
        ys[r][m] = (bt < BT) ? yv[bt*WD + m] : 0.f;
    }
    __syncthreads();
    float acc[32];
    #pragma unroll
    for (int j = 0; j < 32; j++) acc[j] = 0.f;
    for (int m = 0; m < WD; m++) {
        float wvv = Wv[m*LL + l];
        #pragma unroll
        for (int j = 0; j < 32; j++) acc[j] += ys[half*32 + j][m]*wvv;
    }
    float bvl = bv[l];
    int n = l >> 4, e = l & 15;
    #pragma unroll
    for (int j = 0; j < 32; j++) {
        int bt = bt0 + half*32 + j;
        if (bt < BT) {
            int b = bt / T, t = bt % T;
            int idx = ((b*WD + n)*T + t)*EB + e;
            Yout[idx] = Xin[idx] + acc[j] + bvl;
        }
    }
}

// ---------------- decode + time-mix output ----------------
__global__ void k_decode(const float* __restrict__ X, const float* __restrict__ dec_w,
                         const float* __restrict__ dec_b, const float* __restrict__ out_w,
                         const float* __restrict__ out_b, float* __restrict__ out) {
    __shared__ float sy[TF];
    int b = blockIdx.x >> 7, n = blockIdx.x & 127;
    int t = threadIdx.x;
    if (t < TF) {
        const float* xp = X + ((size_t)(b*WD + n)*TF + t)*EB;
        float a = dec_b[n];
        #pragma unroll
        for (int e = 0; e < EB; e++) a += xp[e]*dec_w[n*EB + e];
        sy[t] = a;
    }
    __syncthreads();
    if (t < ODIM) {
        float a = out_b[t];
        for (int tt = 0; tt < TF; tt++) a += sy[tt]*out_w[tt*ODIM + t];
        out[(b*ODIM + t)*WD + n] = a;
    }
}

// ---------------- launcher ----------------
extern "C" void kernel_launch(void* const* d_in, const int* in_sizes, int n_in,
                              void* d_out, int out_size) {
    const float* x_in  = (const float*)d_in[0];
    const float* emb_w = (const float*)d_in[1];
    const float* emb_b = (const float*)d_in[2];
    const float* g0_wf = (const float*)d_in[3];
    const float* g0_bf = (const float*)d_in[4];
    const float* g0_wg = (const float*)d_in[5];
    const float* g0_bg = (const float*)d_in[6];
    const float* g0_ws = (const float*)d_in[7];
    const float* g0_bs = (const float*)d_in[8];
    const float* a0_wq = (const float*)d_in[9];
    const float* a0_bq = (const float*)d_in[10];
    const float* a0_wk = (const float*)d_in[11];
    const float* a0_bk = (const float*)d_in[12];
    const float* a0_wv = (const float*)d_in[13];
    const float* a0_bv = (const float*)d_in[14];
    const float* g1_wf = (const float*)d_in[15];
    const float* g1_bf = (const float*)d_in[16];
    const float* g1_wg = (const float*)d_in[17];
    const float* g1_bg = (const float*)d_in[18];
    const float* g1_ws = (const float*)d_in[19];
    const float* g1_bs = (const float*)d_in[20];
    const float* a1_wq = (const float*)d_in[21];
    const float* a1_bq = (const float*)d_in[22];
    const float* a1_wk = (const float*)d_in[23];
    const float* a1_bk = (const float*)d_in[24];
    const float* a1_wv = (const float*)d_in[25];
    const float* a1_bv = (const float*)d_in[26];
    const float* dec_w = (const float*)d_in[27];
    const float* dec_b = (const float*)d_in[28];
    const float* out_w = (const float*)d_in[29];
    const float* out_b = (const float*)d_in[30];

    float *dA, *dB, *dMt, *dU, *dW, *dC, *dY;
    cudaGetSymbolAddress((void**)&dA,  g_bufA);
    cudaGetSymbolAddress((void**)&dB,  g_bufB);
    cudaGetSymbolAddress((void**)&dMt, g_Mt);
    cudaGetSymbolAddress((void**)&dU,  g_uu);
    cudaGetSymbolAddress((void**)&dW,  g_ww);
    cudaGetSymbolAddress((void**)&dC,  g_cc);
    cudaGetSymbolAddress((void**)&dY,  g_yv);

    // embed + attention precompute (merged launches)
    k_embed<<<(BB*TT0*WD + 255)/256, 256>>>(x_in, emb_w, emb_b, dA);
    k_mt<<<dim3(64,2), 256>>>(a0_wq, a0_wk, a1_wq, a1_wk, dMt);
    k_uw<<<dim3(128,2), 256>>>(a0_wq, a0_wk, a0_bq, a0_bk,
                               a1_wq, a1_wk, a1_bq, a1_bk, dU, dW, dC);

    // layer 0: gated (TIN=128 -> 126, d=2), attention T=126
    {
        const int ntileJ = (126*16 + 63)/64;  // 32
        k_gatedg<128,126,2><<<dim3(ntileJ*2, BB), 128>>>(dA, g0_wf, g0_bf, g0_wg, g0_bg, dB);
        k_res2<128,126><<<BB*32, 256>>>(dA, g0_ws, g0_bs, dB);
        k_attn2<126><<<BB*126, 256>>>(dB, dMt, dU, dW, dC, dY);
        k_attn_out<126><<<dim3(16, (BB*126 + 63)/64), 256>>>(dB, dY, a0_wv, a0_bv, dA);
    }

    // layer 1: gated (TIN=126 -> 122, d=4), attention T=122
    {
        const int ntileJ = (122*16 + 63)/64;  // 31
        k_gatedg<126,122,4><<<dim3(ntileJ*2, BB), 128>>>(dA, g1_wf, g1_bf, g1_wg, g1_bg, dB);
        k_res2<126,122><<<BB*32, 256>>>(dA, g1_ws, g1_bs, dB);
        k_attn2<122><<<BB*122, 256>>>(dB, dMt + WD*WD, dU + WD, dW + WD, dC + 1, dY);
        k_attn_out<122><<<dim3(16, (BB*122 + 63)/64), 256>>>(dB, dY, a1_wv, a1_bv, dA);
    }

    // decode
    k_decode<<<BB*WD, 128>>>(dA, dec_w, dec_b, out_w, out_b, (float*)d_out);
}